// round 14
// baseline (speedup 1.0000x reference)
#include <cuda_runtime.h>
#include <cuda_fp16.h>
#include <cstdint>

// ---------------------------------------------------------------------------
// StabilityGNN round 14: k_main byte-identical (115.6us measured).
// k_h register-blocked: thread = 2 channels x 8 rows -> LDS traffic halved
// (smem crossbar was the binding pipe at ~28us). k_comb split 512 blocks
// (16 rows each) to close its HBM-roofline gap. k_out sums 512 partials.
// ---------------------------------------------------------------------------

#define N_NODES   8192
#define F_IN      256
#define HDIM      128
#define RES2      400
#define C_OUT     10

#define MTILE     128
#define ITILES    (N_NODES / MTILE)    // 64
#define JSPLIT    8
#define JRANGE    (N_NODES / JSPLIT)   // 1024
#define NBLK      (ITILES * JSPLIT)    // 512
#define SCJ       32                   // j per superchunk
#define NSC       (JRANGE / SCJ)       // 32
#define BSTRIDE   40                   // halves per B row (80B)
#define ASTRIDE   36                   // ints per adj row (144B)

// k_main dynamic smem layout: tables + 3 pipeline stages (adj + b_hi)
#define TABB      8192                 // s_tab: 512 x uint4 {sj_h2, f2_h2, df_h2, 0}
#define BHI_O     0
#define ADJ_O     10240
#define STG       28672                // 10240 (bhi) + 18432 (adj)
#define SMEMB     (TABB + 3 * STG)     // 94208

#define ONESH     0x3C003C00u          // half2 {1.0, 1.0}

// k_h config: 32 rows/block, thread = (ch-pair cg 0..63) x (row-octet rg 0..3)
#define KH_ROWS   32
#define KH_BLKS   (N_NODES / KH_ROWS)  // 256
#define RSTRIDE   68                   // padded row stride for reduction (floats)

// k_comb config: 512 blocks x 16 rows
#define CE        8                    // row-eighths per itile
#define NPART     (ITILES * CE)        // 512 partial blocks

// ---------------- device scratch ----------------
__device__ unsigned short g_hT_hi[HDIM * N_NODES];   // [ch][i] fp16
__device__ float g_sic[N_NODES];
__device__ float g_sj[N_NODES];
__device__ float g_e1[N_NODES], g_e2[N_NODES], g_f1[N_NODES], g_f2[N_NODES];
__device__ float g_c;
__device__ float g_pacc[NBLK * MTILE * HDIM];        // partial unnormalized agg
__device__ float g_pl[NBLK * MTILE];                 // partial denominators
__device__ float g_part[NPART * HDIM];

// ---------------- helpers ----------------
__device__ __forceinline__ void mma16816(float* c,
                                         uint32_t a0, uint32_t a1, uint32_t a2, uint32_t a3,
                                         uint32_t b0, uint32_t b1) {
    asm volatile(
        "mma.sync.aligned.m16n8k16.row.col.f32.f16.f16.f32 "
        "{%0,%1,%2,%3}, {%4,%5,%6,%7}, {%8,%9}, {%0,%1,%2,%3};"
        : "+f"(c[0]), "+f"(c[1]), "+f"(c[2]), "+f"(c[3])
        : "r"(a0), "r"(a1), "r"(a2), "r"(a3), "r"(b0), "r"(b1));
}
__device__ __forceinline__ void ldsm_x4(uint32_t& r0, uint32_t& r1,
                                        uint32_t& r2, uint32_t& r3, uint32_t addr) {
    asm volatile("ldmatrix.sync.aligned.m8n8.x4.shared.b16 {%0,%1,%2,%3}, [%4];"
                 : "=r"(r0), "=r"(r1), "=r"(r2), "=r"(r3) : "r"(addr));
}
__device__ __forceinline__ uint32_t h2u(__half2 h) {
    return *reinterpret_cast<uint32_t*>(&h);
}
__device__ __forceinline__ __half2 u2h(uint32_t u) {
    __half2 h; *reinterpret_cast<uint32_t*>(&h) = u; return h;
}
__device__ __forceinline__ uint32_t s2u(const void* p) {
    uint32_t a;
    asm("{ .reg .u64 t; cvta.to.shared.u64 t, %1; cvt.u32.u64 %0, t; }"
        : "=r"(a) : "l"(p));
    return a;
}
__device__ __forceinline__ void cpa16(uint32_t dst, const void* src) {
    asm volatile("cp.async.cg.shared.global [%0], [%1], 16;" :: "r"(dst), "l"(src));
}
__device__ __forceinline__ void cpa_commit() {
    asm volatile("cp.async.commit_group;" ::: "memory");
}
__device__ __forceinline__ void cpa_wait2() {
    asm volatile("cp.async.wait_group 2;" ::: "memory");
}
// int2 (0/1 values) -> half2 {1.0/0.0}
__device__ __forceinline__ uint32_t mask_h2(int ax, int ay) {
    uint32_t m;
    asm("prmt.b32 %0, %1, %2, 0x5410;" : "=r"(m) : "r"(ax), "r"(ay));
    return m * 0x3C00u;
}

// ---------------- k_init ----------------
__global__ void k_init(const float* __restrict__ att, const float* __restrict__ topo) {
    __shared__ float red[128];
    float p = 0.f;
    for (int i = threadIdx.x; i < RES2; i += 128)
        p += att[2 * HDIM + i] * topo[i];
    red[threadIdx.x] = p;
    __syncthreads();
    for (int s = 64; s > 0; s >>= 1) {
        if (threadIdx.x < s) red[threadIdx.x] += red[threadIdx.x + s];
        __syncthreads();
    }
    if (threadIdx.x == 0) g_c = red[0];
}

// ---------------- k_h v3: register-blocked 2ch x 8rows ----------------
// 256 blocks x 256 threads; block owns rows [i0, i0+32).
// Thread (cg = tid&63, rg = tid>>6): channels {2cg, 2cg+1}, rows rg*8..+7.
__global__ __launch_bounds__(256) void k_h(const float* __restrict__ X,
                                           const float* __restrict__ W,
                                           const float* __restrict__ att) {
    __shared__ float Xs[KH_ROWS * F_IN];     // 32 KB; reused as reduction buffer
    __shared__ float srow_i[KH_ROWS], srow_j[KH_ROWS];

    const int tid = threadIdx.x;
    const int i0 = blockIdx.x * KH_ROWS;
    const int cg = tid & 63;
    const int rg = tid >> 6;
    const int ch0 = 2 * cg;
    const int r0 = rg * 8;

    // stage X rows
    for (int idx = tid; idx < KH_ROWS * F_IN / 4; idx += 256)
        ((float4*)Xs)[idx] = ((const float4*)(X + (size_t)i0 * F_IN))[idx];
    __syncthreads();

    float acc0[8], acc1[8];
#pragma unroll
    for (int r = 0; r < 8; r++) { acc0[r] = 0.f; acc1[r] = 0.f; }

    const float4* W0 = (const float4*)(W + (size_t)ch0 * F_IN);
    const float4* W1 = (const float4*)(W + (size_t)(ch0 + 1) * F_IN);
#pragma unroll 2
    for (int f4 = 0; f4 < F_IN / 4; f4++) {
        const float4 wa = W0[f4];
        const float4 wb = W1[f4];
#pragma unroll
        for (int r = 0; r < 8; r++) {
            const float4 x4 = *(const float4*)(Xs + (r0 + r) * F_IN + f4 * 4);
            acc0[r] = fmaf(wa.x, x4.x, acc0[r]);
            acc0[r] = fmaf(wa.y, x4.y, acc0[r]);
            acc0[r] = fmaf(wa.z, x4.z, acc0[r]);
            acc0[r] = fmaf(wa.w, x4.w, acc0[r]);
            acc1[r] = fmaf(wb.x, x4.x, acc1[r]);
            acc1[r] = fmaf(wb.y, x4.y, acc1[r]);
            acc1[r] = fmaf(wb.z, x4.z, acc1[r]);
            acc1[r] = fmaf(wb.w, x4.w, acc1[r]);
        }
    }

    // fp16 transposed write: 8 consecutive i per channel = one uint4 each
    {
        uint4 U0, U1;
        U0.x = h2u(__floats2half2_rn(acc0[0], acc0[1]));
        U0.y = h2u(__floats2half2_rn(acc0[2], acc0[3]));
        U0.z = h2u(__floats2half2_rn(acc0[4], acc0[5]));
        U0.w = h2u(__floats2half2_rn(acc0[6], acc0[7]));
        U1.x = h2u(__floats2half2_rn(acc1[0], acc1[1]));
        U1.y = h2u(__floats2half2_rn(acc1[2], acc1[3]));
        U1.z = h2u(__floats2half2_rn(acc1[4], acc1[5]));
        U1.w = h2u(__floats2half2_rn(acc1[6], acc1[7]));
        *(uint4*)(g_hT_hi + (size_t)ch0 * N_NODES + i0 + r0) = U0;
        *(uint4*)(g_hT_hi + (size_t)(ch0 + 1) * N_NODES + i0 + r0) = U1;
    }

    const float ai0 = att[ch0], ai1 = att[ch0 + 1];
    const float aj0 = att[HDIM + ch0], aj1 = att[HDIM + ch0 + 1];

    // ---- fused s_i reduction: 64 partials per row (RSTRIDE=68 pad) ----
    __syncthreads();                       // everyone done reading Xs
#pragma unroll
    for (int r = 0; r < 8; r++)
        Xs[(r0 + r) * RSTRIDE + cg] = acc0[r] * ai0 + acc1[r] * ai1;
    __syncthreads();
    {
        const int row = tid >> 3, l = tid & 7;
        float s = 0.f;
#pragma unroll
        for (int k = 0; k < 8; k++)
            s += Xs[row * RSTRIDE + l + 8 * k];
        s += __shfl_down_sync(0xFFFFFFFFu, s, 4, 8);
        s += __shfl_down_sync(0xFFFFFFFFu, s, 2, 8);
        s += __shfl_down_sync(0xFFFFFFFFu, s, 1, 8);
        if (l == 0) srow_i[row] = s;
    }
    __syncthreads();

    // ---- fused s_j reduction ----
#pragma unroll
    for (int r = 0; r < 8; r++)
        Xs[(r0 + r) * RSTRIDE + cg] = acc0[r] * aj0 + acc1[r] * aj1;
    __syncthreads();
    {
        const int row = tid >> 3, l = tid & 7;
        float s = 0.f;
#pragma unroll
        for (int k = 0; k < 8; k++)
            s += Xs[row * RSTRIDE + l + 8 * k];
        s += __shfl_down_sync(0xFFFFFFFFu, s, 4, 8);
        s += __shfl_down_sync(0xFFFFFFFFu, s, 2, 8);
        s += __shfl_down_sync(0xFFFFFFFFu, s, 1, 8);
        if (l == 0) srow_j[row] = s;
    }
    __syncthreads();

    // ---- per-row outputs + exp tables ----
    if (tid < KH_ROWS) {
        const int row = i0 + tid;
        const float sic = srow_i[tid] + g_c;
        const float sj = srow_j[tid];
        g_sic[row] = sic;
        g_sj[row] = sj;
        g_e1[row] = __expf(sic);
        g_e2[row] = __expf(0.2f * sic);
        g_f1[row] = __expf(sj);
        g_f2[row] = __expf(0.2f * sj);
    }
}

// ---------------- k_main (byte-identical to rounds 11-13) ----------------
__global__ __launch_bounds__(256, 2) void k_main(const int* __restrict__ adj) {
    extern __shared__ char sm[];
    uint4* s_tab = (uint4*)sm;           // 512 entries

    const int tid = threadIdx.x;
    const int bx = blockIdx.x;
    const int itile = bx >> 3;
    const int jstart = (bx & 7) * JRANGE;
    const int i0 = itile * MTILE;
    const int wid = tid >> 5;
    const int lane = tid & 31;
    const int g = lane >> 2;
    const int tc = lane & 3;

    for (int i = tid; i < JRANGE / 2; i += 256) {
        const int j = jstart + 2 * i;
        const float2 sj2 = *(const float2*)&g_sj[j];
        const float2 f12 = *(const float2*)&g_f1[j];
        const float2 f22 = *(const float2*)&g_f2[j];
        uint4 e;
        e.x = h2u(__floats2half2_rn(sj2.x, sj2.y));
        e.y = h2u(__floats2half2_rn(f22.x, f22.y));
        e.z = h2u(__floats2half2_rn(f12.x - f22.x, f12.y - f22.y));
        e.w = 0;
        s_tab[i] = e;
    }

    const uint32_t sbase = s2u(sm);
    const uint32_t st0 = sbase + TABB;

    auto load_stage = [&](int sc, int buf) {
        const uint32_t sb = st0 + buf * STG;
        const int jb = jstart + sc * SCJ;
#pragma unroll
        for (int q = 0; q < 4; q++) {
            const int idx = q * 256 + tid;
            const int r = idx >> 3, o = idx & 7;
            cpa16(sb + ADJ_O + r * (ASTRIDE * 4) + o * 16,
                  adj + (size_t)(i0 + r) * N_NODES + jb + o * 4);
        }
#pragma unroll
        for (int q = 0; q < 2; q++) {
            const int idx = q * 256 + tid;
            const int r = idx >> 2, o = idx & 3;
            cpa16(sb + BHI_O + r * (BSTRIDE * 2) + o * 16,
                  g_hT_hi + (size_t)r * N_NODES + jb + o * 8);
        }
    };

    const int r0loc = wid * 16 + g;
    const int gr0 = i0 + r0loc;
    const int gr1 = gr0 + 8;
    const __half2 nsic0 = __float2half2_rn(-g_sic[gr0]);
    const __half2 nsic1 = __float2half2_rn(-g_sic[gr1]);
    const float e1v0 = g_e1[gr0], e2v0 = g_e2[gr0];
    const float e1v1 = g_e1[gr1], e2v1 = g_e2[gr1];
    const __half2 e20 = __float2half2_rn(e2v0);
    const __half2 de0 = __float2half2_rn(e1v0 - e2v0);
    const __half2 e21 = __float2half2_rn(e2v1);
    const __half2 de1 = __float2half2_rn(e1v1 - e2v1);

    const uint32_t lane_off =
        (uint32_t)((8 * (lane >> 4) + (lane & 7)) * (BSTRIDE * 2) + ((lane >> 3) & 1) * 16);

    float c[16][4];
#pragma unroll
    for (int t = 0; t < 16; t++)
#pragma unroll
        for (int q = 0; q < 4; q++) c[t][q] = 0.f;
    float c_lp[4] = {0.f, 0.f, 0.f, 0.f};
    float c_cn[4] = {0.f, 0.f, 0.f, 0.f};

    load_stage(0, 0); cpa_commit();
    load_stage(1, 1); cpa_commit();
    load_stage(2, 2); cpa_commit();

#pragma unroll 1
    for (int sc = 0; sc < NSC; ++sc) {
        cpa_wait2();
        __syncthreads();
        const int buf = sc % 3;
        const uint32_t sb = st0 + buf * STG;
        int* adjt = (int*)(sm + TABB + buf * STG + ADJ_O);
        const int jb = jstart + sc * SCJ;

        if (jb < i0 + MTILE && jb + SCJ > i0) {
            if (tid < MTILE) {
                const int d = i0 + tid - jb;
                if (0 <= d && d < SCJ) adjt[tid * ASTRIDE + d] = 0;
            }
            __syncthreads();
        }

#pragma unroll
        for (int ks = 0; ks < 2; ++ks) {
            const int jl2 = ((sc * SCJ + ks * 16) >> 1);
            const uint4 tA = s_tab[jl2 + tc];
            const uint4 tB = s_tab[jl2 + tc + 4];

            const int* a0p = adjt + r0loc * ASTRIDE + ks * 16 + 2 * tc;
            const int2 a00 = *(const int2*)a0p;
            const int2 a01 = *(const int2*)(a0p + 8);
            const int2 a10 = *(const int2*)(a0p + 8 * ASTRIDE);
            const int2 a11 = *(const int2*)(a0p + 8 * ASTRIDE + 8);
            const uint32_t m00 = mask_h2(a00.x, a00.y);
            const uint32_t m01 = mask_h2(a01.x, a01.y);
            const uint32_t m10 = mask_h2(a10.x, a10.y);
            const uint32_t m11 = mask_h2(a11.x, a11.y);

            const __half2 sjA = u2h(tA.x), f2A = u2h(tA.y), dfA = u2h(tA.z);
            const __half2 sjB = u2h(tB.x), f2B = u2h(tB.y), dfB = u2h(tB.z);

            const __half2 pA0 = __hgt2(sjA, nsic0);
            const __half2 pB0 = __hgt2(sjB, nsic0);
            const __half2 pA1 = __hgt2(sjA, nsic1);
            const __half2 pB1 = __hgt2(sjB, nsic1);
            const __half2 wA0 = __hmul2(__hmul2(__hfma2(de0, pA0, e20),
                                                __hfma2(dfA, pA0, f2A)), u2h(m00));
            const __half2 wB0 = __hmul2(__hmul2(__hfma2(de0, pB0, e20),
                                                __hfma2(dfB, pB0, f2B)), u2h(m01));
            const __half2 wA1 = __hmul2(__hmul2(__hfma2(de1, pA1, e21),
                                                __hfma2(dfA, pA1, f2A)), u2h(m10));
            const __half2 wB1 = __hmul2(__hmul2(__hfma2(de1, pB1, e21),
                                                __hfma2(dfB, pB1, f2B)), u2h(m11));
            const uint32_t ah0 = h2u(wA0), ah1 = h2u(wA1);
            const uint32_t ah2 = h2u(wB0), ah3 = h2u(wB1);

            mma16816(c_lp, ah0, ah1, ah2, ah3, ONESH, ONESH);
            mma16816(c_cn, m00, m10, m01, m11, ONESH, ONESH);

            const uint32_t bh = sb + BHI_O + lane_off + ks * 32;
#pragma unroll
            for (int p = 0; p < 8; ++p) {
                uint32_t h0, h1, h2r, h3r;
                ldsm_x4(h0, h1, h2r, h3r, bh + p * (16 * BSTRIDE * 2));
                mma16816(c[2 * p], ah0, ah1, ah2, ah3, h0, h1);
                mma16816(c[2 * p + 1], ah0, ah1, ah2, ah3, h2r, h3r);
            }
        }
        __syncthreads();
        if (sc + 3 < NSC) load_stage(sc + 3, buf);
        cpa_commit();
    }

    if (tc == 0) {
        g_pl[bx * MTILE + r0loc]     = c_lp[0] + ((float)JRANGE - c_cn[0]);
        g_pl[bx * MTILE + r0loc + 8] = c_lp[2] + ((float)JRANGE - c_cn[2]);
    }

    float* base0 = g_pacc + ((size_t)bx * MTILE + r0loc) * HDIM;
    float* base1 = base0 + 8 * HDIM;
#pragma unroll
    for (int t = 0; t < 16; ++t) {
        *(float2*)(base0 + 8 * t + 2 * tc) = make_float2(c[t][0], c[t][1]);
        *(float2*)(base1 + 8 * t + 2 * tc) = make_float2(c[t][2], c[t][3]);
    }
}

// ---------------- k_comb: 512 blocks x 512 threads, 16 rows/block ----------------
// blockIdx.x = it*CE + e; block normalizes rows [e*16, +16) of tile it.
// grp = tid>>7 covers 4 rows each; ch = tid&127.
__global__ __launch_bounds__(512) void k_comb() {
    const int bx = blockIdx.x;
    const int it = bx >> 3;
    const int e = bx & 7;
    const int tid = threadIdx.x;
    const int ch = tid & 127;
    const int grp = tid >> 7;
    __shared__ float sl[16];
    __shared__ float ps[4][HDIM];

    if (tid < 16) {
        const int r = e * 16 + tid;
        float l = 0.f;
#pragma unroll
        for (int s = 0; s < JSPLIT; s++)
            l += g_pl[(it * JSPLIT + s) * MTILE + r];
        sl[tid] = l;
    }
    __syncthreads();

    float psum = 0.f;
#pragma unroll
    for (int rr = 0; rr < 4; rr++) {
        const int rl = grp * 4 + rr;            // 0..15 within eighth
        const int r = e * 16 + rl;              // row within tile
        float a = 0.f;
#pragma unroll
        for (int s = 0; s < JSPLIT; s++)
            a += g_pacc[((size_t)(it * JSPLIT + s) * MTILE + r) * HDIM + ch];
        const float aggv = a / sl[rl];
        psum += (aggv > 0.f) ? aggv : expm1f(aggv);
    }
    ps[grp][ch] = psum;
    __syncthreads();
    if (grp == 0)
        g_part[bx * HDIM + ch] = ps[0][ch] + ps[1][ch] + ps[2][ch] + ps[3][ch];
}

// ---------------- k_out ----------------
__global__ __launch_bounds__(128) void k_out(const float* __restrict__ outW,
                                             const float* __restrict__ outb,
                                             float* __restrict__ out) {
    const int c = threadIdx.x;
    float s = 0.f;
    for (int b = 0; b < NPART; b++) s += g_part[b * HDIM + c];
    const float emb = s * (1.0f / (float)N_NODES);
    __shared__ float red[128];
    for (int k = 0; k < C_OUT; k++) {
        red[c] = emb * outW[k * HDIM + c];
        __syncthreads();
        for (int st = 64; st > 0; st >>= 1) {
            if (c < st) red[c] += red[c + st];
            __syncthreads();
        }
        if (c == 0) out[k] = red[0] + outb[k];
        __syncthreads();
    }
}

// ---------------- launch ----------------
extern "C" void kernel_launch(void* const* d_in, const int* in_sizes, int n_in,
                              void* d_out, int out_size) {
    const float* X    = (const float*)d_in[0];
    const int*   adj  = (const int*)  d_in[1];
    const float* topo = (const float*)d_in[2];
    const float* W    = (const float*)d_in[3];
    const float* att  = (const float*)d_in[4];
    const float* outW = (const float*)d_in[5];
    const float* outb = (const float*)d_in[6];
    float* out = (float*)d_out;

    cudaFuncSetAttribute(k_main, cudaFuncAttributeMaxDynamicSharedMemorySize, SMEMB);

    k_init<<<1, 128>>>(att, topo);
    k_h<<<KH_BLKS, 256>>>(X, W, att);
    k_main<<<NBLK, 256, SMEMB>>>(adj);
    k_comb<<<NPART, 512>>>();
    k_out<<<1, 128>>>(outW, outb, out);
}

// round 15
// speedup vs baseline: 1.0472x; 1.0472x over previous
#include <cuda_runtime.h>
#include <cuda_fp16.h>
#include <cstdint>

// ---------------------------------------------------------------------------
// StabilityGNN round 15: k_h REVERTED to the round-13 version (round-14's
// 2ch-register-blocked variant regressed: the X LDS was warp-broadcast all
// along; the change doubled W LDG traffic instead). k_main byte-identical
// (115.6us). k_comb v3: 512 blocks, thread = 1 row x 4 channels -> 8
// coalesced LDG.128 instead of 32 scalar loads; row-reduction via smem.
// ---------------------------------------------------------------------------

#define N_NODES   8192
#define F_IN      256
#define HDIM      128
#define RES2      400
#define C_OUT     10

#define MTILE     128
#define ITILES    (N_NODES / MTILE)    // 64
#define JSPLIT    8
#define JRANGE    (N_NODES / JSPLIT)   // 1024
#define NBLK      (ITILES * JSPLIT)    // 512
#define SCJ       32                   // j per superchunk
#define NSC       (JRANGE / SCJ)       // 32
#define BSTRIDE   40                   // halves per B row (80B)
#define ASTRIDE   36                   // ints per adj row (144B)

// k_main dynamic smem layout: tables + 3 pipeline stages (adj + b_hi)
#define TABB      8192                 // s_tab: 512 x uint4 {sj_h2, f2_h2, df_h2, 0}
#define BHI_O     0
#define ADJ_O     10240
#define STG       28672                // 10240 (bhi) + 18432 (adj)
#define SMEMB     (TABB + 3 * STG)     // 94208

#define ONESH     0x3C003C00u          // half2 {1.0, 1.0}

// k_h config (round-13 version)
#define KH_ROWS   32
#define KH_BLKS   (N_NODES / KH_ROWS)  // 256
#define RSTRIDE   132                  // padded row stride for reduction (floats)

// k_comb config: 512 blocks x 16 rows
#define CE        8                    // row-eighths per itile
#define NPART     (ITILES * CE)        // 512 partial blocks

// ---------------- device scratch ----------------
__device__ unsigned short g_hT_hi[HDIM * N_NODES];   // [ch][i] fp16
__device__ float g_sic[N_NODES];
__device__ float g_sj[N_NODES];
__device__ float g_e1[N_NODES], g_e2[N_NODES], g_f1[N_NODES], g_f2[N_NODES];
__device__ float g_c;
__device__ float g_pacc[NBLK * MTILE * HDIM];        // partial unnormalized agg
__device__ float g_pl[NBLK * MTILE];                 // partial denominators
__device__ float g_part[NPART * HDIM];

// ---------------- helpers ----------------
__device__ __forceinline__ void mma16816(float* c,
                                         uint32_t a0, uint32_t a1, uint32_t a2, uint32_t a3,
                                         uint32_t b0, uint32_t b1) {
    asm volatile(
        "mma.sync.aligned.m16n8k16.row.col.f32.f16.f16.f32 "
        "{%0,%1,%2,%3}, {%4,%5,%6,%7}, {%8,%9}, {%0,%1,%2,%3};"
        : "+f"(c[0]), "+f"(c[1]), "+f"(c[2]), "+f"(c[3])
        : "r"(a0), "r"(a1), "r"(a2), "r"(a3), "r"(b0), "r"(b1));
}
__device__ __forceinline__ void ldsm_x4(uint32_t& r0, uint32_t& r1,
                                        uint32_t& r2, uint32_t& r3, uint32_t addr) {
    asm volatile("ldmatrix.sync.aligned.m8n8.x4.shared.b16 {%0,%1,%2,%3}, [%4];"
                 : "=r"(r0), "=r"(r1), "=r"(r2), "=r"(r3) : "r"(addr));
}
__device__ __forceinline__ uint32_t h2u(__half2 h) {
    return *reinterpret_cast<uint32_t*>(&h);
}
__device__ __forceinline__ __half2 u2h(uint32_t u) {
    __half2 h; *reinterpret_cast<uint32_t*>(&h) = u; return h;
}
__device__ __forceinline__ uint32_t s2u(const void* p) {
    uint32_t a;
    asm("{ .reg .u64 t; cvta.to.shared.u64 t, %1; cvt.u32.u64 %0, t; }"
        : "=r"(a) : "l"(p));
    return a;
}
__device__ __forceinline__ void cpa16(uint32_t dst, const void* src) {
    asm volatile("cp.async.cg.shared.global [%0], [%1], 16;" :: "r"(dst), "l"(src));
}
__device__ __forceinline__ void cpa_commit() {
    asm volatile("cp.async.commit_group;" ::: "memory");
}
__device__ __forceinline__ void cpa_wait2() {
    asm volatile("cp.async.wait_group 2;" ::: "memory");
}
// int2 (0/1 values) -> half2 {1.0/0.0}
__device__ __forceinline__ uint32_t mask_h2(int ax, int ay) {
    uint32_t m;
    asm("prmt.b32 %0, %1, %2, 0x5410;" : "=r"(m) : "r"(ax), "r"(ay));
    return m * 0x3C00u;
}

// ---------------- k_init ----------------
__global__ void k_init(const float* __restrict__ att, const float* __restrict__ topo) {
    __shared__ float red[128];
    float p = 0.f;
    for (int i = threadIdx.x; i < RES2; i += 128)
        p += att[2 * HDIM + i] * topo[i];
    red[threadIdx.x] = p;
    __syncthreads();
    for (int s = 64; s > 0; s >>= 1) {
        if (threadIdx.x < s) red[threadIdx.x] += red[threadIdx.x + s];
        __syncthreads();
    }
    if (threadIdx.x == 0) g_c = red[0];
}

// ---------------- k_h (round-13 version): 1ch x 16rows + fused s_i/s_j ----------------
__global__ __launch_bounds__(256) void k_h(const float* __restrict__ X,
                                           const float* __restrict__ W,
                                           const float* __restrict__ att) {
    __shared__ float Xs[KH_ROWS * F_IN];     // 32 KB; reused as reduction buffer
    __shared__ float srow_i[KH_ROWS], srow_j[KH_ROWS];

    const int tid = threadIdx.x;
    const int i0 = blockIdx.x * KH_ROWS;
    const int ch = tid & 127;
    const int rh = tid >> 7;
    const int r0 = rh * 16;

    for (int idx = tid; idx < KH_ROWS * F_IN / 4; idx += 256)
        ((float4*)Xs)[idx] = ((const float4*)(X + (size_t)i0 * F_IN))[idx];
    __syncthreads();

    float acc[16];
#pragma unroll
    for (int r = 0; r < 16; r++) acc[r] = 0.f;

    const float4* Wr = (const float4*)(W + (size_t)ch * F_IN);
#pragma unroll 2
    for (int f4 = 0; f4 < F_IN / 4; f4++) {
        const float4 w4 = Wr[f4];
#pragma unroll
        for (int r = 0; r < 16; r++) {
            const float4 x4 = *(const float4*)(Xs + (r0 + r) * F_IN + f4 * 4);
            acc[r] = fmaf(w4.x, x4.x, acc[r]);
            acc[r] = fmaf(w4.y, x4.y, acc[r]);
            acc[r] = fmaf(w4.z, x4.z, acc[r]);
            acc[r] = fmaf(w4.w, x4.w, acc[r]);
        }
    }

    {
        uint32_t p[8];
#pragma unroll
        for (int q = 0; q < 8; q++)
            p[q] = h2u(__floats2half2_rn(acc[2 * q], acc[2 * q + 1]));
        unsigned short* dst = g_hT_hi + (size_t)ch * N_NODES + i0 + r0;
        ((uint4*)dst)[0] = make_uint4(p[0], p[1], p[2], p[3]);
        ((uint4*)dst)[1] = make_uint4(p[4], p[5], p[6], p[7]);
    }

    const float ai = att[ch];
    const float aj = att[HDIM + ch];

    __syncthreads();
#pragma unroll
    for (int r = 0; r < 16; r++)
        Xs[(r0 + r) * RSTRIDE + ch] = acc[r] * ai;
    __syncthreads();
    {
        const int row = tid >> 3, l = tid & 7;
        float s = 0.f;
#pragma unroll
        for (int k = 0; k < 16; k++)
            s += Xs[row * RSTRIDE + l + 8 * k];
        s += __shfl_down_sync(0xFFFFFFFFu, s, 4, 8);
        s += __shfl_down_sync(0xFFFFFFFFu, s, 2, 8);
        s += __shfl_down_sync(0xFFFFFFFFu, s, 1, 8);
        if (l == 0) srow_i[row] = s;
    }
    __syncthreads();

#pragma unroll
    for (int r = 0; r < 16; r++)
        Xs[(r0 + r) * RSTRIDE + ch] = acc[r] * aj;
    __syncthreads();
    {
        const int row = tid >> 3, l = tid & 7;
        float s = 0.f;
#pragma unroll
        for (int k = 0; k < 16; k++)
            s += Xs[row * RSTRIDE + l + 8 * k];
        s += __shfl_down_sync(0xFFFFFFFFu, s, 4, 8);
        s += __shfl_down_sync(0xFFFFFFFFu, s, 2, 8);
        s += __shfl_down_sync(0xFFFFFFFFu, s, 1, 8);
        if (l == 0) srow_j[row] = s;
    }
    __syncthreads();

    if (tid < KH_ROWS) {
        const int row = i0 + tid;
        const float sic = srow_i[tid] + g_c;
        const float sj = srow_j[tid];
        g_sic[row] = sic;
        g_sj[row] = sj;
        g_e1[row] = __expf(sic);
        g_e2[row] = __expf(0.2f * sic);
        g_f1[row] = __expf(sj);
        g_f2[row] = __expf(0.2f * sj);
    }
}

// ---------------- k_main (byte-identical to rounds 11-14) ----------------
__global__ __launch_bounds__(256, 2) void k_main(const int* __restrict__ adj) {
    extern __shared__ char sm[];
    uint4* s_tab = (uint4*)sm;           // 512 entries

    const int tid = threadIdx.x;
    const int bx = blockIdx.x;
    const int itile = bx >> 3;
    const int jstart = (bx & 7) * JRANGE;
    const int i0 = itile * MTILE;
    const int wid = tid >> 5;
    const int lane = tid & 31;
    const int g = lane >> 2;
    const int tc = lane & 3;

    for (int i = tid; i < JRANGE / 2; i += 256) {
        const int j = jstart + 2 * i;
        const float2 sj2 = *(const float2*)&g_sj[j];
        const float2 f12 = *(const float2*)&g_f1[j];
        const float2 f22 = *(const float2*)&g_f2[j];
        uint4 e;
        e.x = h2u(__floats2half2_rn(sj2.x, sj2.y));
        e.y = h2u(__floats2half2_rn(f22.x, f22.y));
        e.z = h2u(__floats2half2_rn(f12.x - f22.x, f12.y - f22.y));
        e.w = 0;
        s_tab[i] = e;
    }

    const uint32_t sbase = s2u(sm);
    const uint32_t st0 = sbase + TABB;

    auto load_stage = [&](int sc, int buf) {
        const uint32_t sb = st0 + buf * STG;
        const int jb = jstart + sc * SCJ;
#pragma unroll
        for (int q = 0; q < 4; q++) {
            const int idx = q * 256 + tid;
            const int r = idx >> 3, o = idx & 7;
            cpa16(sb + ADJ_O + r * (ASTRIDE * 4) + o * 16,
                  adj + (size_t)(i0 + r) * N_NODES + jb + o * 4);
        }
#pragma unroll
        for (int q = 0; q < 2; q++) {
            const int idx = q * 256 + tid;
            const int r = idx >> 2, o = idx & 3;
            cpa16(sb + BHI_O + r * (BSTRIDE * 2) + o * 16,
                  g_hT_hi + (size_t)r * N_NODES + jb + o * 8);
        }
    };

    const int r0loc = wid * 16 + g;
    const int gr0 = i0 + r0loc;
    const int gr1 = gr0 + 8;
    const __half2 nsic0 = __float2half2_rn(-g_sic[gr0]);
    const __half2 nsic1 = __float2half2_rn(-g_sic[gr1]);
    const float e1v0 = g_e1[gr0], e2v0 = g_e2[gr0];
    const float e1v1 = g_e1[gr1], e2v1 = g_e2[gr1];
    const __half2 e20 = __float2half2_rn(e2v0);
    const __half2 de0 = __float2half2_rn(e1v0 - e2v0);
    const __half2 e21 = __float2half2_rn(e2v1);
    const __half2 de1 = __float2half2_rn(e1v1 - e2v1);

    const uint32_t lane_off =
        (uint32_t)((8 * (lane >> 4) + (lane & 7)) * (BSTRIDE * 2) + ((lane >> 3) & 1) * 16);

    float c[16][4];
#pragma unroll
    for (int t = 0; t < 16; t++)
#pragma unroll
        for (int q = 0; q < 4; q++) c[t][q] = 0.f;
    float c_lp[4] = {0.f, 0.f, 0.f, 0.f};
    float c_cn[4] = {0.f, 0.f, 0.f, 0.f};

    load_stage(0, 0); cpa_commit();
    load_stage(1, 1); cpa_commit();
    load_stage(2, 2); cpa_commit();

#pragma unroll 1
    for (int sc = 0; sc < NSC; ++sc) {
        cpa_wait2();
        __syncthreads();
        const int buf = sc % 3;
        const uint32_t sb = st0 + buf * STG;
        int* adjt = (int*)(sm + TABB + buf * STG + ADJ_O);
        const int jb = jstart + sc * SCJ;

        if (jb < i0 + MTILE && jb + SCJ > i0) {
            if (tid < MTILE) {
                const int d = i0 + tid - jb;
                if (0 <= d && d < SCJ) adjt[tid * ASTRIDE + d] = 0;
            }
            __syncthreads();
        }

#pragma unroll
        for (int ks = 0; ks < 2; ++ks) {
            const int jl2 = ((sc * SCJ + ks * 16) >> 1);
            const uint4 tA = s_tab[jl2 + tc];
            const uint4 tB = s_tab[jl2 + tc + 4];

            const int* a0p = adjt + r0loc * ASTRIDE + ks * 16 + 2 * tc;
            const int2 a00 = *(const int2*)a0p;
            const int2 a01 = *(const int2*)(a0p + 8);
            const int2 a10 = *(const int2*)(a0p + 8 * ASTRIDE);
            const int2 a11 = *(const int2*)(a0p + 8 * ASTRIDE + 8);
            const uint32_t m00 = mask_h2(a00.x, a00.y);
            const uint32_t m01 = mask_h2(a01.x, a01.y);
            const uint32_t m10 = mask_h2(a10.x, a10.y);
            const uint32_t m11 = mask_h2(a11.x, a11.y);

            const __half2 sjA = u2h(tA.x), f2A = u2h(tA.y), dfA = u2h(tA.z);
            const __half2 sjB = u2h(tB.x), f2B = u2h(tB.y), dfB = u2h(tB.z);

            const __half2 pA0 = __hgt2(sjA, nsic0);
            const __half2 pB0 = __hgt2(sjB, nsic0);
            const __half2 pA1 = __hgt2(sjA, nsic1);
            const __half2 pB1 = __hgt2(sjB, nsic1);
            const __half2 wA0 = __hmul2(__hmul2(__hfma2(de0, pA0, e20),
                                                __hfma2(dfA, pA0, f2A)), u2h(m00));
            const __half2 wB0 = __hmul2(__hmul2(__hfma2(de0, pB0, e20),
                                                __hfma2(dfB, pB0, f2B)), u2h(m01));
            const __half2 wA1 = __hmul2(__hmul2(__hfma2(de1, pA1, e21),
                                                __hfma2(dfA, pA1, f2A)), u2h(m10));
            const __half2 wB1 = __hmul2(__hmul2(__hfma2(de1, pB1, e21),
                                                __hfma2(dfB, pB1, f2B)), u2h(m11));
            const uint32_t ah0 = h2u(wA0), ah1 = h2u(wA1);
            const uint32_t ah2 = h2u(wB0), ah3 = h2u(wB1);

            mma16816(c_lp, ah0, ah1, ah2, ah3, ONESH, ONESH);
            mma16816(c_cn, m00, m10, m01, m11, ONESH, ONESH);

            const uint32_t bh = sb + BHI_O + lane_off + ks * 32;
#pragma unroll
            for (int p = 0; p < 8; ++p) {
                uint32_t h0, h1, h2r, h3r;
                ldsm_x4(h0, h1, h2r, h3r, bh + p * (16 * BSTRIDE * 2));
                mma16816(c[2 * p], ah0, ah1, ah2, ah3, h0, h1);
                mma16816(c[2 * p + 1], ah0, ah1, ah2, ah3, h2r, h3r);
            }
        }
        __syncthreads();
        if (sc + 3 < NSC) load_stage(sc + 3, buf);
        cpa_commit();
    }

    if (tc == 0) {
        g_pl[bx * MTILE + r0loc]     = c_lp[0] + ((float)JRANGE - c_cn[0]);
        g_pl[bx * MTILE + r0loc + 8] = c_lp[2] + ((float)JRANGE - c_cn[2]);
    }

    float* base0 = g_pacc + ((size_t)bx * MTILE + r0loc) * HDIM;
    float* base1 = base0 + 8 * HDIM;
#pragma unroll
    for (int t = 0; t < 16; ++t) {
        *(float2*)(base0 + 8 * t + 2 * tc) = make_float2(c[t][0], c[t][1]);
        *(float2*)(base1 + 8 * t + 2 * tc) = make_float2(c[t][2], c[t][3]);
    }
}

// ---------------- k_comb v3: 512 blocks x 512 threads, float4 loads ----------------
// blockIdx.x = it*CE + e; block handles rows [e*16, +16) of tile it.
// Thread = (quad = tid&31 -> channels quad*4..+3, rl = tid>>5 -> one row).
// 8 coalesced LDG.128 per thread; row reduction staged through smem.
__global__ __launch_bounds__(512) void k_comb() {
    const int bx = blockIdx.x;
    const int it = bx >> 3;
    const int e = bx & 7;
    const int tid = threadIdx.x;
    const int quad = tid & 31;
    const int rl = tid >> 5;             // 0..15
    __shared__ float sl[16];
    __shared__ float pr[16][HDIM];       // 8 KB elu'd row values
    __shared__ float ps[4][HDIM];

    if (tid < 16) {
        const int r = e * 16 + tid;
        float l = 0.f;
#pragma unroll
        for (int s = 0; s < JSPLIT; s++)
            l += g_pl[(it * JSPLIT + s) * MTILE + r];
        sl[tid] = l;
    }
    __syncthreads();

    const int r = e * 16 + rl;
    float4 a = make_float4(0.f, 0.f, 0.f, 0.f);
#pragma unroll
    for (int s = 0; s < JSPLIT; s++) {
        const float4 v = *(const float4*)&g_pacc[
            ((size_t)(it * JSPLIT + s) * MTILE + r) * HDIM + quad * 4];
        a.x += v.x; a.y += v.y; a.z += v.z; a.w += v.w;
    }
    const float l = sl[rl];
    float4 o;
    o.x = a.x / l; o.y = a.y / l; o.z = a.z / l; o.w = a.w / l;
    o.x = (o.x > 0.f) ? o.x : expm1f(o.x);
    o.y = (o.y > 0.f) ? o.y : expm1f(o.y);
    o.z = (o.z > 0.f) ? o.z : expm1f(o.z);
    o.w = (o.w > 0.f) ? o.w : expm1f(o.w);
    *(float4*)&pr[rl][quad * 4] = o;
    __syncthreads();

    // reduce 16 rows -> per-channel sums
    const int ch = tid & 127;
    const int gr = tid >> 7;             // 0..3, rows gr*4..+3
    ps[gr][ch] = pr[gr * 4 + 0][ch] + pr[gr * 4 + 1][ch] +
                 pr[gr * 4 + 2][ch] + pr[gr * 4 + 3][ch];
    __syncthreads();
    if (gr == 0)
        g_part[bx * HDIM + ch] = ps[0][ch] + ps[1][ch] + ps[2][ch] + ps[3][ch];
}

// ---------------- k_out ----------------
__global__ __launch_bounds__(128) void k_out(const float* __restrict__ outW,
                                             const float* __restrict__ outb,
                                             float* __restrict__ out) {
    const int c = threadIdx.x;
    float s = 0.f;
    for (int b = 0; b < NPART; b++) s += g_part[b * HDIM + c];
    const float emb = s * (1.0f / (float)N_NODES);
    __shared__ float red[128];
    for (int k = 0; k < C_OUT; k++) {
        red[c] = emb * outW[k * HDIM + c];
        __syncthreads();
        for (int st = 64; st > 0; st >>= 1) {
            if (c < st) red[c] += red[c + st];
            __syncthreads();
        }
        if (c == 0) out[k] = red[0] + outb[k];
        __syncthreads();
    }
}

// ---------------- launch ----------------
extern "C" void kernel_launch(void* const* d_in, const int* in_sizes, int n_in,
                              void* d_out, int out_size) {
    const float* X    = (const float*)d_in[0];
    const int*   adj  = (const int*)  d_in[1];
    const float* topo = (const float*)d_in[2];
    const float* W    = (const float*)d_in[3];
    const float* att  = (const float*)d_in[4];
    const float* outW = (const float*)d_in[5];
    const float* outb = (const float*)d_in[6];
    float* out = (float*)d_out;

    cudaFuncSetAttribute(k_main, cudaFuncAttributeMaxDynamicSharedMemorySize, SMEMB);

    k_init<<<1, 128>>>(att, topo);
    k_h<<<KH_BLKS, 256>>>(X, W, att);
    k_main<<<NBLK, 256, SMEMB>>>(adj);
    k_comb<<<NPART, 512>>>();
    k_out<<<1, 128>>>(outW, outb, out);
}

// round 16
// speedup vs baseline: 1.0985x; 1.0490x over previous
#include <cuda_runtime.h>
#include <cuda_fp16.h>
#include <cstdint>

// ---------------------------------------------------------------------------
// StabilityGNN round 16: k_h = round-13 (measured good), k_comb = round-15 v3
// (11.2us measured). k_main: SCJ 32->64 with 2-deep cp.async pipeline —
// halves the __syncthreads cadence (2 per 64 j instead of 4) and doubles the
// inter-barrier desync window to 4 ksteps, attacking the measured lockstep
// stall (issue 26%, tensor 31% at 16 warps/SM). Numerics bit-identical.
// Smem: 8192 + 2*53248 = 114688 B/CTA -> 2 CTAs = 224KB <= 228KB/SM.
// ---------------------------------------------------------------------------

#define N_NODES   8192
#define F_IN      256
#define HDIM      128
#define RES2      400
#define C_OUT     10

#define MTILE     128
#define ITILES    (N_NODES / MTILE)    // 64
#define JSPLIT    8
#define JRANGE    (N_NODES / JSPLIT)   // 1024
#define NBLK      (ITILES * JSPLIT)    // 512
#define SCJ       64                   // j per superchunk (was 32)
#define NSC       (JRANGE / SCJ)       // 16
#define BSTRIDE   72                   // halves per B row (144B, 16B-mult, LDSM-safe)
#define ASTRIDE   68                   // ints per adj row (272B, 16B-mult, g*16 banks)

// k_main dynamic smem layout: tables + 2 pipeline stages (b_hi + adj)
#define TABB      8192                 // s_tab: 512 x uint4 {sj_h2, f2_h2, df_h2, 0}
#define BHI_O     0
#define ADJ_O     18432                // 128 * 72 * 2
#define STG       53248                // 18432 (bhi) + 34816 (adj)
#define SMEMB     (TABB + 2 * STG)     // 114688

#define ONESH     0x3C003C00u          // half2 {1.0, 1.0}

// k_h config (round-13 version)
#define KH_ROWS   32
#define KH_BLKS   (N_NODES / KH_ROWS)  // 256
#define RSTRIDE   132                  // padded row stride for reduction (floats)

// k_comb config: 512 blocks x 16 rows
#define CE        8                    // row-eighths per itile
#define NPART     (ITILES * CE)        // 512 partial blocks

// ---------------- device scratch ----------------
__device__ unsigned short g_hT_hi[HDIM * N_NODES];   // [ch][i] fp16
__device__ float g_sic[N_NODES];
__device__ float g_sj[N_NODES];
__device__ float g_e1[N_NODES], g_e2[N_NODES], g_f1[N_NODES], g_f2[N_NODES];
__device__ float g_c;
__device__ float g_pacc[NBLK * MTILE * HDIM];        // partial unnormalized agg
__device__ float g_pl[NBLK * MTILE];                 // partial denominators
__device__ float g_part[NPART * HDIM];

// ---------------- helpers ----------------
__device__ __forceinline__ void mma16816(float* c,
                                         uint32_t a0, uint32_t a1, uint32_t a2, uint32_t a3,
                                         uint32_t b0, uint32_t b1) {
    asm volatile(
        "mma.sync.aligned.m16n8k16.row.col.f32.f16.f16.f32 "
        "{%0,%1,%2,%3}, {%4,%5,%6,%7}, {%8,%9}, {%0,%1,%2,%3};"
        : "+f"(c[0]), "+f"(c[1]), "+f"(c[2]), "+f"(c[3])
        : "r"(a0), "r"(a1), "r"(a2), "r"(a3), "r"(b0), "r"(b1));
}
__device__ __forceinline__ void ldsm_x4(uint32_t& r0, uint32_t& r1,
                                        uint32_t& r2, uint32_t& r3, uint32_t addr) {
    asm volatile("ldmatrix.sync.aligned.m8n8.x4.shared.b16 {%0,%1,%2,%3}, [%4];"
                 : "=r"(r0), "=r"(r1), "=r"(r2), "=r"(r3) : "r"(addr));
}
__device__ __forceinline__ uint32_t h2u(__half2 h) {
    return *reinterpret_cast<uint32_t*>(&h);
}
__device__ __forceinline__ __half2 u2h(uint32_t u) {
    __half2 h; *reinterpret_cast<uint32_t*>(&h) = u; return h;
}
__device__ __forceinline__ uint32_t s2u(const void* p) {
    uint32_t a;
    asm("{ .reg .u64 t; cvta.to.shared.u64 t, %1; cvt.u32.u64 %0, t; }"
        : "=r"(a) : "l"(p));
    return a;
}
__device__ __forceinline__ void cpa16(uint32_t dst, const void* src) {
    asm volatile("cp.async.cg.shared.global [%0], [%1], 16;" :: "r"(dst), "l"(src));
}
__device__ __forceinline__ void cpa_commit() {
    asm volatile("cp.async.commit_group;" ::: "memory");
}
__device__ __forceinline__ void cpa_wait1() {
    asm volatile("cp.async.wait_group 1;" ::: "memory");
}
// int2 (0/1 values) -> half2 {1.0/0.0}
__device__ __forceinline__ uint32_t mask_h2(int ax, int ay) {
    uint32_t m;
    asm("prmt.b32 %0, %1, %2, 0x5410;" : "=r"(m) : "r"(ax), "r"(ay));
    return m * 0x3C00u;
}

// ---------------- k_init ----------------
__global__ void k_init(const float* __restrict__ att, const float* __restrict__ topo) {
    __shared__ float red[128];
    float p = 0.f;
    for (int i = threadIdx.x; i < RES2; i += 128)
        p += att[2 * HDIM + i] * topo[i];
    red[threadIdx.x] = p;
    __syncthreads();
    for (int s = 64; s > 0; s >>= 1) {
        if (threadIdx.x < s) red[threadIdx.x] += red[threadIdx.x + s];
        __syncthreads();
    }
    if (threadIdx.x == 0) g_c = red[0];
}

// ---------------- k_h (round-13 version): 1ch x 16rows + fused s_i/s_j ----------------
__global__ __launch_bounds__(256) void k_h(const float* __restrict__ X,
                                           const float* __restrict__ W,
                                           const float* __restrict__ att) {
    __shared__ float Xs[KH_ROWS * F_IN];     // 32 KB; reused as reduction buffer
    __shared__ float srow_i[KH_ROWS], srow_j[KH_ROWS];

    const int tid = threadIdx.x;
    const int i0 = blockIdx.x * KH_ROWS;
    const int ch = tid & 127;
    const int rh = tid >> 7;
    const int r0 = rh * 16;

    for (int idx = tid; idx < KH_ROWS * F_IN / 4; idx += 256)
        ((float4*)Xs)[idx] = ((const float4*)(X + (size_t)i0 * F_IN))[idx];
    __syncthreads();

    float acc[16];
#pragma unroll
    for (int r = 0; r < 16; r++) acc[r] = 0.f;

    const float4* Wr = (const float4*)(W + (size_t)ch * F_IN);
#pragma unroll 2
    for (int f4 = 0; f4 < F_IN / 4; f4++) {
        const float4 w4 = Wr[f4];
#pragma unroll
        for (int r = 0; r < 16; r++) {
            const float4 x4 = *(const float4*)(Xs + (r0 + r) * F_IN + f4 * 4);
            acc[r] = fmaf(w4.x, x4.x, acc[r]);
            acc[r] = fmaf(w4.y, x4.y, acc[r]);
            acc[r] = fmaf(w4.z, x4.z, acc[r]);
            acc[r] = fmaf(w4.w, x4.w, acc[r]);
        }
    }

    {
        uint32_t p[8];
#pragma unroll
        for (int q = 0; q < 8; q++)
            p[q] = h2u(__floats2half2_rn(acc[2 * q], acc[2 * q + 1]));
        unsigned short* dst = g_hT_hi + (size_t)ch * N_NODES + i0 + r0;
        ((uint4*)dst)[0] = make_uint4(p[0], p[1], p[2], p[3]);
        ((uint4*)dst)[1] = make_uint4(p[4], p[5], p[6], p[7]);
    }

    const float ai = att[ch];
    const float aj = att[HDIM + ch];

    __syncthreads();
#pragma unroll
    for (int r = 0; r < 16; r++)
        Xs[(r0 + r) * RSTRIDE + ch] = acc[r] * ai;
    __syncthreads();
    {
        const int row = tid >> 3, l = tid & 7;
        float s = 0.f;
#pragma unroll
        for (int k = 0; k < 16; k++)
            s += Xs[row * RSTRIDE + l + 8 * k];
        s += __shfl_down_sync(0xFFFFFFFFu, s, 4, 8);
        s += __shfl_down_sync(0xFFFFFFFFu, s, 2, 8);
        s += __shfl_down_sync(0xFFFFFFFFu, s, 1, 8);
        if (l == 0) srow_i[row] = s;
    }
    __syncthreads();

#pragma unroll
    for (int r = 0; r < 16; r++)
        Xs[(r0 + r) * RSTRIDE + ch] = acc[r] * aj;
    __syncthreads();
    {
        const int row = tid >> 3, l = tid & 7;
        float s = 0.f;
#pragma unroll
        for (int k = 0; k < 16; k++)
            s += Xs[row * RSTRIDE + l + 8 * k];
        s += __shfl_down_sync(0xFFFFFFFFu, s, 4, 8);
        s += __shfl_down_sync(0xFFFFFFFFu, s, 2, 8);
        s += __shfl_down_sync(0xFFFFFFFFu, s, 1, 8);
        if (l == 0) srow_j[row] = s;
    }
    __syncthreads();

    if (tid < KH_ROWS) {
        const int row = i0 + tid;
        const float sic = srow_i[tid] + g_c;
        const float sj = srow_j[tid];
        g_sic[row] = sic;
        g_sj[row] = sj;
        g_e1[row] = __expf(sic);
        g_e2[row] = __expf(0.2f * sic);
        g_f1[row] = __expf(sj);
        g_f2[row] = __expf(0.2f * sj);
    }
}

// ---------------- k_main: SCJ=64, 2-deep pipeline ----------------
__global__ __launch_bounds__(256, 2) void k_main(const int* __restrict__ adj) {
    extern __shared__ char sm[];
    uint4* s_tab = (uint4*)sm;           // 512 entries

    const int tid = threadIdx.x;
    const int bx = blockIdx.x;
    const int itile = bx >> 3;
    const int jstart = (bx & 7) * JRANGE;
    const int i0 = itile * MTILE;
    const int wid = tid >> 5;
    const int lane = tid & 31;
    const int g = lane >> 2;
    const int tc = lane & 3;

    // pack j tables: {sj, f2, f1-f2} as half2 per j-pair
    for (int i = tid; i < JRANGE / 2; i += 256) {
        const int j = jstart + 2 * i;
        const float2 sj2 = *(const float2*)&g_sj[j];
        const float2 f12 = *(const float2*)&g_f1[j];
        const float2 f22 = *(const float2*)&g_f2[j];
        uint4 e;
        e.x = h2u(__floats2half2_rn(sj2.x, sj2.y));
        e.y = h2u(__floats2half2_rn(f22.x, f22.y));
        e.z = h2u(__floats2half2_rn(f12.x - f22.x, f12.y - f22.y));
        e.w = 0;
        s_tab[i] = e;
    }

    const uint32_t sbase = s2u(sm);
    const uint32_t st0 = sbase + TABB;

    // ---- cp.async staging of one 64-j superchunk ----
    auto load_stage = [&](int sc, int buf) {
        const uint32_t sb = st0 + buf * STG;
        const int jb = jstart + sc * SCJ;
        // adj: 128 rows x 64 ints = 2048 x 16B chunks (16 per row)
#pragma unroll
        for (int q = 0; q < 8; q++) {
            const int idx = q * 256 + tid;
            const int r = idx >> 4, o = idx & 15;
            cpa16(sb + ADJ_O + r * (ASTRIDE * 4) + o * 16,
                  adj + (size_t)(i0 + r) * N_NODES + jb + o * 4);
        }
        // b_hi: 128 rows x 64 halves = 1024 x 16B chunks (8 per row)
#pragma unroll
        for (int q = 0; q < 4; q++) {
            const int idx = q * 256 + tid;
            const int r = idx >> 3, o = idx & 7;
            cpa16(sb + BHI_O + r * (BSTRIDE * 2) + o * 16,
                  g_hT_hi + (size_t)r * N_NODES + jb + o * 8);
        }
    };

    const int r0loc = wid * 16 + g;
    const int gr0 = i0 + r0loc;
    const int gr1 = gr0 + 8;
    const __half2 nsic0 = __float2half2_rn(-g_sic[gr0]);
    const __half2 nsic1 = __float2half2_rn(-g_sic[gr1]);
    const float e1v0 = g_e1[gr0], e2v0 = g_e2[gr0];
    const float e1v1 = g_e1[gr1], e2v1 = g_e2[gr1];
    const __half2 e20 = __float2half2_rn(e2v0);
    const __half2 de0 = __float2half2_rn(e1v0 - e2v0);
    const __half2 e21 = __float2half2_rn(e2v1);
    const __half2 de1 = __float2half2_rn(e1v1 - e2v1);

    // ldmatrix lane offset (bytes): rows 8*(L>>4) + (L&7); unit1 -> +16B
    const uint32_t lane_off =
        (uint32_t)((8 * (lane >> 4) + (lane & 7)) * (BSTRIDE * 2) + ((lane >> 3) & 1) * 16);

    float c[16][4];
#pragma unroll
    for (int t = 0; t < 16; t++)
#pragma unroll
        for (int q = 0; q < 4; q++) c[t][q] = 0.f;
    float c_lp[4] = {0.f, 0.f, 0.f, 0.f};
    float c_cn[4] = {0.f, 0.f, 0.f, 0.f};

    // prologue: 2 stages in flight
    load_stage(0, 0); cpa_commit();
    load_stage(1, 1); cpa_commit();

#pragma unroll 1
    for (int sc = 0; sc < NSC; ++sc) {
        cpa_wait1();                 // stage sc landed
        __syncthreads();
        const int buf = sc & 1;
        const uint32_t sb = st0 + buf * STG;
        int* adjt = (int*)(sm + TABB + buf * STG + ADJ_O);
        const int jb = jstart + sc * SCJ;

        // zero diagonal entries in smem (only superchunks intersecting the i-range)
        if (jb < i0 + MTILE && jb + SCJ > i0) {
            if (tid < MTILE) {
                const int d = i0 + tid - jb;
                if (0 <= d && d < SCJ) adjt[tid * ASTRIDE + d] = 0;
            }
            __syncthreads();
        }

#pragma unroll
        for (int ks = 0; ks < 4; ++ks) {
            const int jl2 = ((sc * SCJ + ks * 16) >> 1);
            const uint4 tA = s_tab[jl2 + tc];
            const uint4 tB = s_tab[jl2 + tc + 4];

            const int* a0p = adjt + r0loc * ASTRIDE + ks * 16 + 2 * tc;
            const int2 a00 = *(const int2*)a0p;
            const int2 a01 = *(const int2*)(a0p + 8);
            const int2 a10 = *(const int2*)(a0p + 8 * ASTRIDE);
            const int2 a11 = *(const int2*)(a0p + 8 * ASTRIDE + 8);
            const uint32_t m00 = mask_h2(a00.x, a00.y);
            const uint32_t m01 = mask_h2(a01.x, a01.y);
            const uint32_t m10 = mask_h2(a10.x, a10.y);
            const uint32_t m11 = mask_h2(a11.x, a11.y);

            const __half2 sjA = u2h(tA.x), f2A = u2h(tA.y), dfA = u2h(tA.z);
            const __half2 sjB = u2h(tB.x), f2B = u2h(tB.y), dfB = u2h(tB.z);

            const __half2 pA0 = __hgt2(sjA, nsic0);
            const __half2 pB0 = __hgt2(sjB, nsic0);
            const __half2 pA1 = __hgt2(sjA, nsic1);
            const __half2 pB1 = __hgt2(sjB, nsic1);
            const __half2 wA0 = __hmul2(__hmul2(__hfma2(de0, pA0, e20),
                                                __hfma2(dfA, pA0, f2A)), u2h(m00));
            const __half2 wB0 = __hmul2(__hmul2(__hfma2(de0, pB0, e20),
                                                __hfma2(dfB, pB0, f2B)), u2h(m01));
            const __half2 wA1 = __hmul2(__hmul2(__hfma2(de1, pA1, e21),
                                                __hfma2(dfA, pA1, f2A)), u2h(m10));
            const __half2 wB1 = __hmul2(__hmul2(__hfma2(de1, pB1, e21),
                                                __hfma2(dfB, pB1, f2B)), u2h(m11));
            const uint32_t ah0 = h2u(wA0), ah1 = h2u(wA1);
            const uint32_t ah2 = h2u(wB0), ah3 = h2u(wB1);

            // denominators: sum of the same fp16 weights + exact edge count
            mma16816(c_lp, ah0, ah1, ah2, ah3, ONESH, ONESH);
            mma16816(c_cn, m00, m10, m01, m11, ONESH, ONESH);

            const uint32_t bh = sb + BHI_O + lane_off + ks * 32;
#pragma unroll
            for (int p = 0; p < 8; ++p) {
                uint32_t h0, h1, h2r, h3r;
                ldsm_x4(h0, h1, h2r, h3r, bh + p * (16 * BSTRIDE * 2));
                mma16816(c[2 * p], ah0, ah1, ah2, ah3, h0, h1);
                mma16816(c[2 * p + 1], ah0, ah1, ah2, ah3, h2r, h3r);
            }
        }
        __syncthreads();                 // all warps done reading this buffer
        if (sc + 2 < NSC) load_stage(sc + 2, buf);
        cpa_commit();                    // keep group count consistent
    }

    // denominators: lp + (JRANGE - edge_count)
    if (tc == 0) {
        g_pl[bx * MTILE + r0loc]     = c_lp[0] + ((float)JRANGE - c_cn[0]);
        g_pl[bx * MTILE + r0loc + 8] = c_lp[2] + ((float)JRANGE - c_cn[2]);
    }

    // partial (unnormalized) aggregation
    float* base0 = g_pacc + ((size_t)bx * MTILE + r0loc) * HDIM;
    float* base1 = base0 + 8 * HDIM;
#pragma unroll
    for (int t = 0; t < 16; ++t) {
        *(float2*)(base0 + 8 * t + 2 * tc) = make_float2(c[t][0], c[t][1]);
        *(float2*)(base1 + 8 * t + 2 * tc) = make_float2(c[t][2], c[t][3]);
    }
}

// ---------------- k_comb v3 (round-15, measured 11.2us) ----------------
__global__ __launch_bounds__(512) void k_comb() {
    const int bx = blockIdx.x;
    const int it = bx >> 3;
    const int e = bx & 7;
    const int tid = threadIdx.x;
    const int quad = tid & 31;
    const int rl = tid >> 5;             // 0..15
    __shared__ float sl[16];
    __shared__ float pr[16][HDIM];       // 8 KB elu'd row values
    __shared__ float ps[4][HDIM];

    if (tid < 16) {
        const int r = e * 16 + tid;
        float l = 0.f;
#pragma unroll
        for (int s = 0; s < JSPLIT; s++)
            l += g_pl[(it * JSPLIT + s) * MTILE + r];
        sl[tid] = l;
    }
    __syncthreads();

    const int r = e * 16 + rl;
    float4 a = make_float4(0.f, 0.f, 0.f, 0.f);
#pragma unroll
    for (int s = 0; s < JSPLIT; s++) {
        const float4 v = *(const float4*)&g_pacc[
            ((size_t)(it * JSPLIT + s) * MTILE + r) * HDIM + quad * 4];
        a.x += v.x; a.y += v.y; a.z += v.z; a.w += v.w;
    }
    const float l = sl[rl];
    float4 o;
    o.x = a.x / l; o.y = a.y / l; o.z = a.z / l; o.w = a.w / l;
    o.x = (o.x > 0.f) ? o.x : expm1f(o.x);
    o.y = (o.y > 0.f) ? o.y : expm1f(o.y);
    o.z = (o.z > 0.f) ? o.z : expm1f(o.z);
    o.w = (o.w > 0.f) ? o.w : expm1f(o.w);
    *(float4*)&pr[rl][quad * 4] = o;
    __syncthreads();

    const int ch = tid & 127;
    const int gr = tid >> 7;             // 0..3, rows gr*4..+3
    ps[gr][ch] = pr[gr * 4 + 0][ch] + pr[gr * 4 + 1][ch] +
                 pr[gr * 4 + 2][ch] + pr[gr * 4 + 3][ch];
    __syncthreads();
    if (gr == 0)
        g_part[bx * HDIM + ch] = ps[0][ch] + ps[1][ch] + ps[2][ch] + ps[3][ch];
}

// ---------------- k_out ----------------
__global__ __launch_bounds__(128) void k_out(const float* __restrict__ outW,
                                             const float* __restrict__ outb,
                                             float* __restrict__ out) {
    const int c = threadIdx.x;
    float s = 0.f;
    for (int b = 0; b < NPART; b++) s += g_part[b * HDIM + c];
    const float emb = s * (1.0f / (float)N_NODES);
    __shared__ float red[128];
    for (int k = 0; k < C_OUT; k++) {
        red[c] = emb * outW[k * HDIM + c];
        __syncthreads();
        for (int st = 64; st > 0; st >>= 1) {
            if (c < st) red[c] += red[c + st];
            __syncthreads();
        }
        if (c == 0) out[k] = red[0] + outb[k];
        __syncthreads();
    }
}

// ---------------- launch ----------------
extern "C" void kernel_launch(void* const* d_in, const int* in_sizes, int n_in,
                              void* d_out, int out_size) {
    const float* X    = (const float*)d_in[0];
    const int*   adj  = (const int*)  d_in[1];
    const float* topo = (const float*)d_in[2];
    const float* W    = (const float*)d_in[3];
    const float* att  = (const float*)d_in[4];
    const float* outW = (const float*)d_in[5];
    const float* outb = (const float*)d_in[6];
    float* out = (float*)d_out;

    cudaFuncSetAttribute(k_main, cudaFuncAttributeMaxDynamicSharedMemorySize, SMEMB);

    k_init<<<1, 128>>>(att, topo);
    k_h<<<KH_BLKS, 256>>>(X, W, att);
    k_main<<<NBLK, 256, SMEMB>>>(adj);
    k_comb<<<NPART, 512>>>();
    k_out<<<1, 128>>>(outW, outb, out);
}

// round 17
// speedup vs baseline: 1.0999x; 1.0013x over previous
#include <cuda_runtime.h>
#include <cuda_fp16.h>
#include <cstdint>

// ---------------------------------------------------------------------------
// StabilityGNN round 17: k_main (SCJ=64, round-16 measured win), k_comb v3,
// k_out unchanged. k_h v4: X staged TRANSPOSED in smem (Xs[f*34+r]) so a
// row-pair at feature f is one LDS.64, feeding packed fma.rn.f32x2 —
// 2048 FFMA2/thread instead of 4096 scalar FFMA. Per-row accumulation order
// identical -> h bit-identical -> rel_err unchanged (1.4310e-4).
// ---------------------------------------------------------------------------

#define N_NODES   8192
#define F_IN      256
#define HDIM      128
#define RES2      400
#define C_OUT     10

#define MTILE     128
#define ITILES    (N_NODES / MTILE)    // 64
#define JSPLIT    8
#define JRANGE    (N_NODES / JSPLIT)   // 1024
#define NBLK      (ITILES * JSPLIT)    // 512
#define SCJ       64                   // j per superchunk
#define NSC       (JRANGE / SCJ)       // 16
#define BSTRIDE   72                   // halves per B row (144B)
#define ASTRIDE   68                   // ints per adj row (272B)

// k_main dynamic smem layout: tables + 2 pipeline stages (b_hi + adj)
#define TABB      8192
#define BHI_O     0
#define ADJ_O     18432                // 128 * 72 * 2
#define STG       53248                // 18432 (bhi) + 34816 (adj)
#define SMEMB     (TABB + 2 * STG)     // 114688

#define ONESH     0x3C003C00u          // half2 {1.0, 1.0}

// k_h config
#define KH_ROWS   32
#define KH_BLKS   (N_NODES / KH_ROWS)  // 256
#define XSTRIDE   34                   // floats per transposed feature row (8B-aligned pairs)
#define RSTRIDE   132                  // padded row stride for reduction (floats)

// k_comb config: 512 blocks x 16 rows
#define CE        8
#define NPART     (ITILES * CE)        // 512

// ---------------- device scratch ----------------
__device__ unsigned short g_hT_hi[HDIM * N_NODES];   // [ch][i] fp16
__device__ float g_sic[N_NODES];
__device__ float g_sj[N_NODES];
__device__ float g_e1[N_NODES], g_e2[N_NODES], g_f1[N_NODES], g_f2[N_NODES];
__device__ float g_c;
__device__ float g_pacc[NBLK * MTILE * HDIM];
__device__ float g_pl[NBLK * MTILE];
__device__ float g_part[NPART * HDIM];

// ---------------- helpers ----------------
__device__ __forceinline__ void mma16816(float* c,
                                         uint32_t a0, uint32_t a1, uint32_t a2, uint32_t a3,
                                         uint32_t b0, uint32_t b1) {
    asm volatile(
        "mma.sync.aligned.m16n8k16.row.col.f32.f16.f16.f32 "
        "{%0,%1,%2,%3}, {%4,%5,%6,%7}, {%8,%9}, {%0,%1,%2,%3};"
        : "+f"(c[0]), "+f"(c[1]), "+f"(c[2]), "+f"(c[3])
        : "r"(a0), "r"(a1), "r"(a2), "r"(a3), "r"(b0), "r"(b1));
}
__device__ __forceinline__ void ldsm_x4(uint32_t& r0, uint32_t& r1,
                                        uint32_t& r2, uint32_t& r3, uint32_t addr) {
    asm volatile("ldmatrix.sync.aligned.m8n8.x4.shared.b16 {%0,%1,%2,%3}, [%4];"
                 : "=r"(r0), "=r"(r1), "=r"(r2), "=r"(r3) : "r"(addr));
}
__device__ __forceinline__ uint32_t h2u(__half2 h) {
    return *reinterpret_cast<uint32_t*>(&h);
}
__device__ __forceinline__ __half2 u2h(uint32_t u) {
    __half2 h; *reinterpret_cast<uint32_t*>(&h) = u; return h;
}
__device__ __forceinline__ uint32_t s2u(const void* p) {
    uint32_t a;
    asm("{ .reg .u64 t; cvta.to.shared.u64 t, %1; cvt.u32.u64 %0, t; }"
        : "=r"(a) : "l"(p));
    return a;
}
__device__ __forceinline__ void cpa16(uint32_t dst, const void* src) {
    asm volatile("cp.async.cg.shared.global [%0], [%1], 16;" :: "r"(dst), "l"(src));
}
__device__ __forceinline__ void cpa_commit() {
    asm volatile("cp.async.commit_group;" ::: "memory");
}
__device__ __forceinline__ void cpa_wait1() {
    asm volatile("cp.async.wait_group 1;" ::: "memory");
}
__device__ __forceinline__ uint32_t mask_h2(int ax, int ay) {
    uint32_t m;
    asm("prmt.b32 %0, %1, %2, 0x5410;" : "=r"(m) : "r"(ax), "r"(ay));
    return m * 0x3C00u;
}
// packed f32x2 helpers
__device__ __forceinline__ unsigned long long pack2(float lo, float hi) {
    unsigned long long r;
    asm("mov.b64 %0, {%1, %2};" : "=l"(r) : "f"(lo), "f"(hi));
    return r;
}
__device__ __forceinline__ unsigned long long ffma2(unsigned long long a,
                                                    unsigned long long b,
                                                    unsigned long long c) {
    unsigned long long d;
    asm("fma.rn.f32x2 %0, %1, %2, %3;" : "=l"(d) : "l"(a), "l"(b), "l"(c));
    return d;
}
__device__ __forceinline__ float2 unpack2(unsigned long long v) {
    float2 r;
    asm("mov.b64 {%0, %1}, %2;" : "=f"(r.x), "=f"(r.y) : "l"(v));
    return r;
}

// ---------------- k_init ----------------
__global__ void k_init(const float* __restrict__ att, const float* __restrict__ topo) {
    __shared__ float red[128];
    float p = 0.f;
    for (int i = threadIdx.x; i < RES2; i += 128)
        p += att[2 * HDIM + i] * topo[i];
    red[threadIdx.x] = p;
    __syncthreads();
    for (int s = 64; s > 0; s >>= 1) {
        if (threadIdx.x < s) red[threadIdx.x] += red[threadIdx.x + s];
        __syncthreads();
    }
    if (threadIdx.x == 0) g_c = red[0];
}

// ---------------- k_h v4: transposed X + f32x2 FMAs + fused s_i/s_j ----------------
// 256 blocks x 256 threads; block owns rows [i0, i0+32).
// Thread (ch = tid&127, rh = tid>>7): channel ch, rows rh*16 .. +15.
__global__ __launch_bounds__(256) void k_h(const float* __restrict__ X,
                                           const float* __restrict__ W,
                                           const float* __restrict__ att) {
    __shared__ float Xs[F_IN * XSTRIDE];     // 34816 B, transposed [f][r]; reused for reduce
    __shared__ float srow_i[KH_ROWS], srow_j[KH_ROWS];

    const int tid = threadIdx.x;
    const int i0 = blockIdx.x * KH_ROWS;
    const int ch = tid & 127;
    const int rh = tid >> 7;
    const int r0 = rh * 16;

    // stage X transposed: Xs[f*XSTRIDE + r] = X[i0+r][f]
    // (reads coalesced over f; writes 2-way-conflict scalar STS)
    for (int idx = tid; idx < KH_ROWS * F_IN; idx += 256) {
        const int r = idx >> 8;              // 0..31
        const int f = idx & 255;
        Xs[f * XSTRIDE + r] = X[(size_t)(i0 + r) * F_IN + f];
    }
    __syncthreads();

    // 8 row-pair accumulators (packed f32x2)
    unsigned long long acc2[8];
#pragma unroll
    for (int p = 0; p < 8; p++) acc2[p] = 0ull;

    const float4* Wr = (const float4*)(W + (size_t)ch * F_IN);
#pragma unroll 2
    for (int f4 = 0; f4 < F_IN / 4; f4++) {
        const float4 w4 = Wr[f4];
        const unsigned long long wp0 = pack2(w4.x, w4.x);
        const unsigned long long wp1 = pack2(w4.y, w4.y);
        const unsigned long long wp2 = pack2(w4.z, w4.z);
        const unsigned long long wp3 = pack2(w4.w, w4.w);
        const float* b0 = Xs + (f4 * 4 + 0) * XSTRIDE + r0;
        const float* b1 = Xs + (f4 * 4 + 1) * XSTRIDE + r0;
        const float* b2 = Xs + (f4 * 4 + 2) * XSTRIDE + r0;
        const float* b3 = Xs + (f4 * 4 + 3) * XSTRIDE + r0;
#pragma unroll
        for (int p = 0; p < 8; p++) {
            acc2[p] = ffma2(wp0, *(const unsigned long long*)(b0 + 2 * p), acc2[p]);
            acc2[p] = ffma2(wp1, *(const unsigned long long*)(b1 + 2 * p), acc2[p]);
            acc2[p] = ffma2(wp2, *(const unsigned long long*)(b2 + 2 * p), acc2[p]);
            acc2[p] = ffma2(wp3, *(const unsigned long long*)(b3 + 2 * p), acc2[p]);
        }
    }

    // unpack to 16 per-row values (bit-identical to scalar accumulation order)
    float acc[16];
#pragma unroll
    for (int p = 0; p < 8; p++) {
        const float2 v = unpack2(acc2[p]);
        acc[2 * p] = v.x;
        acc[2 * p + 1] = v.y;
    }

    // fp16 transposed write: 16 consecutive i for this channel
    {
        uint32_t pk[8];
#pragma unroll
        for (int q = 0; q < 8; q++)
            pk[q] = h2u(__floats2half2_rn(acc[2 * q], acc[2 * q + 1]));
        unsigned short* dst = g_hT_hi + (size_t)ch * N_NODES + i0 + r0;
        ((uint4*)dst)[0] = make_uint4(pk[0], pk[1], pk[2], pk[3]);
        ((uint4*)dst)[1] = make_uint4(pk[4], pk[5], pk[6], pk[7]);
    }

    const float ai = att[ch];
    const float aj = att[HDIM + ch];

    // ---- fused s_i reduction (reuse Xs; RSTRIDE padding) ----
    __syncthreads();                       // everyone done reading Xs
#pragma unroll
    for (int r = 0; r < 16; r++)
        Xs[(r0 + r) * RSTRIDE + ch] = acc[r] * ai;
    __syncthreads();
    {
        const int row = tid >> 3, l = tid & 7;
        float s = 0.f;
#pragma unroll
        for (int k = 0; k < 16; k++)
            s += Xs[row * RSTRIDE + l + 8 * k];
        s += __shfl_down_sync(0xFFFFFFFFu, s, 4, 8);
        s += __shfl_down_sync(0xFFFFFFFFu, s, 2, 8);
        s += __shfl_down_sync(0xFFFFFFFFu, s, 1, 8);
        if (l == 0) srow_i[row] = s;
    }
    __syncthreads();

    // ---- fused s_j reduction ----
#pragma unroll
    for (int r = 0; r < 16; r++)
        Xs[(r0 + r) * RSTRIDE + ch] = acc[r] * aj;
    __syncthreads();
    {
        const int row = tid >> 3, l = tid & 7;
        float s = 0.f;
#pragma unroll
        for (int k = 0; k < 16; k++)
            s += Xs[row * RSTRIDE + l + 8 * k];
        s += __shfl_down_sync(0xFFFFFFFFu, s, 4, 8);
        s += __shfl_down_sync(0xFFFFFFFFu, s, 2, 8);
        s += __shfl_down_sync(0xFFFFFFFFu, s, 1, 8);
        if (l == 0) srow_j[row] = s;
    }
    __syncthreads();

    if (tid < KH_ROWS) {
        const int row = i0 + tid;
        const float sic = srow_i[tid] + g_c;
        const float sj = srow_j[tid];
        g_sic[row] = sic;
        g_sj[row] = sj;
        g_e1[row] = __expf(sic);
        g_e2[row] = __expf(0.2f * sic);
        g_f1[row] = __expf(sj);
        g_f2[row] = __expf(0.2f * sj);
    }
}

// ---------------- k_main (byte-identical to round 16) ----------------
__global__ __launch_bounds__(256, 2) void k_main(const int* __restrict__ adj) {
    extern __shared__ char sm[];
    uint4* s_tab = (uint4*)sm;           // 512 entries

    const int tid = threadIdx.x;
    const int bx = blockIdx.x;
    const int itile = bx >> 3;
    const int jstart = (bx & 7) * JRANGE;
    const int i0 = itile * MTILE;
    const int wid = tid >> 5;
    const int lane = tid & 31;
    const int g = lane >> 2;
    const int tc = lane & 3;

    for (int i = tid; i < JRANGE / 2; i += 256) {
        const int j = jstart + 2 * i;
        const float2 sj2 = *(const float2*)&g_sj[j];
        const float2 f12 = *(const float2*)&g_f1[j];
        const float2 f22 = *(const float2*)&g_f2[j];
        uint4 e;
        e.x = h2u(__floats2half2_rn(sj2.x, sj2.y));
        e.y = h2u(__floats2half2_rn(f22.x, f22.y));
        e.z = h2u(__floats2half2_rn(f12.x - f22.x, f12.y - f22.y));
        e.w = 0;
        s_tab[i] = e;
    }

    const uint32_t sbase = s2u(sm);
    const uint32_t st0 = sbase + TABB;

    auto load_stage = [&](int sc, int buf) {
        const uint32_t sb = st0 + buf * STG;
        const int jb = jstart + sc * SCJ;
#pragma unroll
        for (int q = 0; q < 8; q++) {
            const int idx = q * 256 + tid;
            const int r = idx >> 4, o = idx & 15;
            cpa16(sb + ADJ_O + r * (ASTRIDE * 4) + o * 16,
                  adj + (size_t)(i0 + r) * N_NODES + jb + o * 4);
        }
#pragma unroll
        for (int q = 0; q < 4; q++) {
            const int idx = q * 256 + tid;
            const int r = idx >> 3, o = idx & 7;
            cpa16(sb + BHI_O + r * (BSTRIDE * 2) + o * 16,
                  g_hT_hi + (size_t)r * N_NODES + jb + o * 8);
        }
    };

    const int r0loc = wid * 16 + g;
    const int gr0 = i0 + r0loc;
    const int gr1 = gr0 + 8;
    const __half2 nsic0 = __float2half2_rn(-g_sic[gr0]);
    const __half2 nsic1 = __float2half2_rn(-g_sic[gr1]);
    const float e1v0 = g_e1[gr0], e2v0 = g_e2[gr0];
    const float e1v1 = g_e1[gr1], e2v1 = g_e2[gr1];
    const __half2 e20 = __float2half2_rn(e2v0);
    const __half2 de0 = __float2half2_rn(e1v0 - e2v0);
    const __half2 e21 = __float2half2_rn(e2v1);
    const __half2 de1 = __float2half2_rn(e1v1 - e2v1);

    const uint32_t lane_off =
        (uint32_t)((8 * (lane >> 4) + (lane & 7)) * (BSTRIDE * 2) + ((lane >> 3) & 1) * 16);

    float c[16][4];
#pragma unroll
    for (int t = 0; t < 16; t++)
#pragma unroll
        for (int q = 0; q < 4; q++) c[t][q] = 0.f;
    float c_lp[4] = {0.f, 0.f, 0.f, 0.f};
    float c_cn[4] = {0.f, 0.f, 0.f, 0.f};

    load_stage(0, 0); cpa_commit();
    load_stage(1, 1); cpa_commit();

#pragma unroll 1
    for (int sc = 0; sc < NSC; ++sc) {
        cpa_wait1();
        __syncthreads();
        const int buf = sc & 1;
        const uint32_t sb = st0 + buf * STG;
        int* adjt = (int*)(sm + TABB + buf * STG + ADJ_O);
        const int jb = jstart + sc * SCJ;

        if (jb < i0 + MTILE && jb + SCJ > i0) {
            if (tid < MTILE) {
                const int d = i0 + tid - jb;
                if (0 <= d && d < SCJ) adjt[tid * ASTRIDE + d] = 0;
            }
            __syncthreads();
        }

#pragma unroll
        for (int ks = 0; ks < 4; ++ks) {
            const int jl2 = ((sc * SCJ + ks * 16) >> 1);
            const uint4 tA = s_tab[jl2 + tc];
            const uint4 tB = s_tab[jl2 + tc + 4];

            const int* a0p = adjt + r0loc * ASTRIDE + ks * 16 + 2 * tc;
            const int2 a00 = *(const int2*)a0p;
            const int2 a01 = *(const int2*)(a0p + 8);
            const int2 a10 = *(const int2*)(a0p + 8 * ASTRIDE);
            const int2 a11 = *(const int2*)(a0p + 8 * ASTRIDE + 8);
            const uint32_t m00 = mask_h2(a00.x, a00.y);
            const uint32_t m01 = mask_h2(a01.x, a01.y);
            const uint32_t m10 = mask_h2(a10.x, a10.y);
            const uint32_t m11 = mask_h2(a11.x, a11.y);

            const __half2 sjA = u2h(tA.x), f2A = u2h(tA.y), dfA = u2h(tA.z);
            const __half2 sjB = u2h(tB.x), f2B = u2h(tB.y), dfB = u2h(tB.z);

            const __half2 pA0 = __hgt2(sjA, nsic0);
            const __half2 pB0 = __hgt2(sjB, nsic0);
            const __half2 pA1 = __hgt2(sjA, nsic1);
            const __half2 pB1 = __hgt2(sjB, nsic1);
            const __half2 wA0 = __hmul2(__hmul2(__hfma2(de0, pA0, e20),
                                                __hfma2(dfA, pA0, f2A)), u2h(m00));
            const __half2 wB0 = __hmul2(__hmul2(__hfma2(de0, pB0, e20),
                                                __hfma2(dfB, pB0, f2B)), u2h(m01));
            const __half2 wA1 = __hmul2(__hmul2(__hfma2(de1, pA1, e21),
                                                __hfma2(dfA, pA1, f2A)), u2h(m10));
            const __half2 wB1 = __hmul2(__hmul2(__hfma2(de1, pB1, e21),
                                                __hfma2(dfB, pB1, f2B)), u2h(m11));
            const uint32_t ah0 = h2u(wA0), ah1 = h2u(wA1);
            const uint32_t ah2 = h2u(wB0), ah3 = h2u(wB1);

            mma16816(c_lp, ah0, ah1, ah2, ah3, ONESH, ONESH);
            mma16816(c_cn, m00, m10, m01, m11, ONESH, ONESH);

            const uint32_t bh = sb + BHI_O + lane_off + ks * 32;
#pragma unroll
            for (int p = 0; p < 8; ++p) {
                uint32_t h0, h1, h2r, h3r;
                ldsm_x4(h0, h1, h2r, h3r, bh + p * (16 * BSTRIDE * 2));
                mma16816(c[2 * p], ah0, ah1, ah2, ah3, h0, h1);
                mma16816(c[2 * p + 1], ah0, ah1, ah2, ah3, h2r, h3r);
            }
        }
        __syncthreads();
        if (sc + 2 < NSC) load_stage(sc + 2, buf);
        cpa_commit();
    }

    if (tc == 0) {
        g_pl[bx * MTILE + r0loc]     = c_lp[0] + ((float)JRANGE - c_cn[0]);
        g_pl[bx * MTILE + r0loc + 8] = c_lp[2] + ((float)JRANGE - c_cn[2]);
    }

    float* base0 = g_pacc + ((size_t)bx * MTILE + r0loc) * HDIM;
    float* base1 = base0 + 8 * HDIM;
#pragma unroll
    for (int t = 0; t < 16; ++t) {
        *(float2*)(base0 + 8 * t + 2 * tc) = make_float2(c[t][0], c[t][1]);
        *(float2*)(base1 + 8 * t + 2 * tc) = make_float2(c[t][2], c[t][3]);
    }
}

// ---------------- k_comb v3 (round-15/16, measured) ----------------
__global__ __launch_bounds__(512) void k_comb() {
    const int bx = blockIdx.x;
    const int it = bx >> 3;
    const int e = bx & 7;
    const int tid = threadIdx.x;
    const int quad = tid & 31;
    const int rl = tid >> 5;             // 0..15
    __shared__ float sl[16];
    __shared__ float pr[16][HDIM];
    __shared__ float ps[4][HDIM];

    if (tid < 16) {
        const int r = e * 16 + tid;
        float l = 0.f;
#pragma unroll
        for (int s = 0; s < JSPLIT; s++)
            l += g_pl[(it * JSPLIT + s) * MTILE + r];
        sl[tid] = l;
    }
    __syncthreads();

    const int r = e * 16 + rl;
    float4 a = make_float4(0.f, 0.f, 0.f, 0.f);
#pragma unroll
    for (int s = 0; s < JSPLIT; s++) {
        const float4 v = *(const float4*)&g_pacc[
            ((size_t)(it * JSPLIT + s) * MTILE + r) * HDIM + quad * 4];
        a.x += v.x; a.y += v.y; a.z += v.z; a.w += v.w;
    }
    const float l = sl[rl];
    float4 o;
    o.x = a.x / l; o.y = a.y / l; o.z = a.z / l; o.w = a.w / l;
    o.x = (o.x > 0.f) ? o.x : expm1f(o.x);
    o.y = (o.y > 0.f) ? o.y : expm1f(o.y);
    o.z = (o.z > 0.f) ? o.z : expm1f(o.z);
    o.w = (o.w > 0.f) ? o.w : expm1f(o.w);
    *(float4*)&pr[rl][quad * 4] = o;
    __syncthreads();

    const int ch = tid & 127;
    const int gr = tid >> 7;
    ps[gr][ch] = pr[gr * 4 + 0][ch] + pr[gr * 4 + 1][ch] +
                 pr[gr * 4 + 2][ch] + pr[gr * 4 + 3][ch];
    __syncthreads();
    if (gr == 0)
        g_part[bx * HDIM + ch] = ps[0][ch] + ps[1][ch] + ps[2][ch] + ps[3][ch];
}

// ---------------- k_out ----------------
__global__ __launch_bounds__(128) void k_out(const float* __restrict__ outW,
                                             const float* __restrict__ outb,
                                             float* __restrict__ out) {
    const int c = threadIdx.x;
    float s = 0.f;
    for (int b = 0; b < NPART; b++) s += g_part[b * HDIM + c];
    const float emb = s * (1.0f / (float)N_NODES);
    __shared__ float red[128];
    for (int k = 0; k < C_OUT; k++) {
        red[c] = emb * outW[k * HDIM + c];
        __syncthreads();
        for (int st = 64; st > 0; st >>= 1) {
            if (c < st) red[c] += red[c + st];
            __syncthreads();
        }
        if (c == 0) out[k] = red[0] + outb[k];
        __syncthreads();
    }
}

// ---------------- launch ----------------
extern "C" void kernel_launch(void* const* d_in, const int* in_sizes, int n_in,
                              void* d_out, int out_size) {
    const float* X    = (const float*)d_in[0];
    const int*   adj  = (const int*)  d_in[1];
    const float* topo = (const float*)d_in[2];
    const float* W    = (const float*)d_in[3];
    const float* att  = (const float*)d_in[4];
    const float* outW = (const float*)d_in[5];
    const float* outb = (const float*)d_in[6];
    float* out = (float*)d_out;

    cudaFuncSetAttribute(k_main, cudaFuncAttributeMaxDynamicSharedMemorySize, SMEMB);

    k_init<<<1, 128>>>(att, topo);
    k_h<<<KH_BLKS, 256>>>(X, W, att);
    k_main<<<NBLK, 256, SMEMB>>>(adj);
    k_comb<<<NPART, 512>>>();
    k_out<<<1, 128>>>(outW, outb, out);
}